// round 1
// baseline (speedup 1.0000x reference)
#include <cuda_runtime.h>
#include <cuda_bf16.h>
#include <math.h>

// Problem constants
#define B_   64
#define T_   256
#define E_   300
#define H_   256
#define G4H  1024      // 4*H
#define INTER_ 128
#define NL   17
#define TL   19        // NUM_LABELS + 2
#define START_L 17
#define END_L   18
#define LOW_POT (-10000.0f)

// ---------------- scratch (device globals; no allocations allowed) ----------
__device__ float g_xproj[(size_t)2 * T_ * G4H * B_];   // [dir][t][n(1024)][b]  134MB
__device__ float g_h[(size_t)2 * T_ * H_ * B_];        // [dir][t][k][b]        33.5MB
__device__ float g_inter[(size_t)T_ * INTER_ * B_];    // [t][n(128)][b]        8.4MB
__device__ float g_unary[(size_t)B_ * T_ * TL];        // [b][t][l]             1.2MB
__device__ int   g_bar[2 * 4 * T_];                    // per-(dir,batchgroup) step counters

// ---------------- barrier zeroing (graph-replay determinism) ----------------
__global__ void zero_bar_kernel() {
    int i = blockIdx.x * 256 + threadIdx.x;
    if (i < 2 * 4 * T_) g_bar[i] = 0;
}

// ---------------- x_proj GEMM: out[dir][t][n][b] = W_ih[n,:]·emb[b,t,:] + b[n]
// grid (16 n-tiles, 256 t, 2 dir), block 256. Tile 64(n) x 64(b), K=300 (5 chunks of 64, zero-padded).
__global__ void xproj_kernel(const int* __restrict__ x,
                             const float* __restrict__ emb,
                             const float* __restrict__ Wf, const float* __restrict__ bf,
                             const float* __restrict__ Wb, const float* __restrict__ bb) {
    __shared__ int   tok[64];
    __shared__ float As[64 * 64];   // [k][n]
    __shared__ float Bs[64 * 64];   // [k][b]
    const int tid = threadIdx.x;
    const int n0  = blockIdx.x * 64;
    const int t   = blockIdx.y;
    const int dir = blockIdx.z;
    const float* W    = dir ? Wb : Wf;
    const float* bias = dir ? bb : bf;

    if (tid < 64) tok[tid] = x[tid * T_ + t];
    __syncthreads();

    float acc[4][4];
#pragma unroll
    for (int i = 0; i < 4; i++)
#pragma unroll
        for (int j = 0; j < 4; j++) acc[i][j] = 0.f;

    const int lane = tid & 63;       // n for A-load, b for B-load
    const int k4b  = tid >> 6;       // 0..3
    const int n_t  = tid >> 4;       // 0..15
    const int b_t  = tid & 15;       // 0..15

    for (int kc = 0; kc < 5; kc++) {
        const int k0 = kc * 64;
        // ---- A tile: W[n0+lane][k0..k0+63] -> As[k][n]
        const float* Arow = W + (size_t)(n0 + lane) * E_;
#pragma unroll
        for (int i = 0; i < 4; i++) {
            int k4 = k4b + i * 4;
            int k  = k0 + k4 * 4;
            float4 v;
            if (k + 3 < E_) {
                v = *(const float4*)(Arow + k);
            } else {
                v.x = (k     < E_) ? Arow[k]     : 0.f;
                v.y = (k + 1 < E_) ? Arow[k + 1] : 0.f;
                v.z = (k + 2 < E_) ? Arow[k + 2] : 0.f;
                v.w = (k + 3 < E_) ? Arow[k + 3] : 0.f;
            }
            As[(k4 * 4 + 0) * 64 + lane] = v.x;
            As[(k4 * 4 + 1) * 64 + lane] = v.y;
            As[(k4 * 4 + 2) * 64 + lane] = v.z;
            As[(k4 * 4 + 3) * 64 + lane] = v.w;
        }
        // ---- B tile: emb[tok[lane]][k0..k0+63] -> Bs[k][b]
        const float* Brow = emb + (size_t)tok[lane] * E_;
#pragma unroll
        for (int i = 0; i < 4; i++) {
            int k4 = k4b + i * 4;
            int k  = k0 + k4 * 4;
            float4 v;
            if (k + 3 < E_) {
                v = *(const float4*)(Brow + k);
            } else {
                v.x = (k     < E_) ? Brow[k]     : 0.f;
                v.y = (k + 1 < E_) ? Brow[k + 1] : 0.f;
                v.z = (k + 2 < E_) ? Brow[k + 2] : 0.f;
                v.w = (k + 3 < E_) ? Brow[k + 3] : 0.f;
            }
            Bs[(k4 * 4 + 0) * 64 + lane] = v.x;
            Bs[(k4 * 4 + 1) * 64 + lane] = v.y;
            Bs[(k4 * 4 + 2) * 64 + lane] = v.z;
            Bs[(k4 * 4 + 3) * 64 + lane] = v.w;
        }
        __syncthreads();

        const float4* A4 = (const float4*)As;
        const float4* B4 = (const float4*)Bs;
#pragma unroll 4
        for (int k = 0; k < 64; k++) {
            float4 a = A4[k * 16 + n_t];
            float4 b = B4[k * 16 + b_t];
            acc[0][0] += a.x * b.x; acc[0][1] += a.x * b.y; acc[0][2] += a.x * b.z; acc[0][3] += a.x * b.w;
            acc[1][0] += a.y * b.x; acc[1][1] += a.y * b.y; acc[1][2] += a.y * b.z; acc[1][3] += a.y * b.w;
            acc[2][0] += a.z * b.x; acc[2][1] += a.z * b.y; acc[2][2] += a.z * b.z; acc[2][3] += a.z * b.w;
            acc[3][0] += a.w * b.x; acc[3][1] += a.w * b.y; acc[3][2] += a.w * b.z; acc[3][3] += a.w * b.w;
        }
        __syncthreads();
    }
    // epilogue: + bias, write [dir][t][n][b]
    float* outb = g_xproj + (((size_t)dir * T_ + t) * G4H + n0 + n_t * 4) * B_ + b_t * 4;
#pragma unroll
    for (int j = 0; j < 4; j++) {
        float bv = bias[n0 + n_t * 4 + j];
        float4 o;
        o.x = acc[j][0] + bv; o.y = acc[j][1] + bv; o.z = acc[j][2] + bv; o.w = acc[j][3] + bv;
        *(float4*)(outb + (size_t)j * B_) = o;
    }
}

// ---------------- LSTM recurrence (persistent, per-group sync) --------------
__device__ __forceinline__ float sigf(float x) { return 1.0f / (1.0f + expf(-x)); }

// grid 128 blocks: dir(2) x batchgroup(4, 16 batches) x hiddenchunk(16, 16 dims).
// block 256 threads = (k_i 16) x (b_i 16). Each thread owns one (batch, hidden) cell:
// 4 gate accumulators, c in register. W_hh slice (64 rows x 256) in smem.
__global__ void lstm_kernel(const float* __restrict__ Whf, const float* __restrict__ Whb) {
    extern __shared__ float sm[];
    float* w  = sm;              // [64][256]: row q*16+ki
    float* hs = sm + 64 * 256;   // [256][16]: [kk][bi]

    const int tid = threadIdx.x;
    const int bx  = blockIdx.x;
    const int dir = bx >> 6;
    const int r   = bx & 63;
    const int bg  = r >> 4;       // 0..3
    const int hc  = r & 15;       // 0..15
    const float* Wh = dir ? Whb : Whf;

    // load weight slice: rows (q*256 + hc*16 + ki) for q in 0..3, ki in 0..15
#pragma unroll
    for (int i = 0; i < 16; i++) {
        int f4id = tid + i * 256;           // 0..4095
        int rr = f4id >> 6;                 // 0..63 local row
        int c4 = f4id & 63;
        int q  = rr >> 4, ki = rr & 15;
        float4 v = *(const float4*)(Wh + ((size_t)(q * H_ + hc * 16 + ki)) * H_ + c4 * 4);
        *(float4*)(w + (size_t)rr * 256 + c4 * 4) = v;
    }

    const int bi = tid & 15;
    const int ki = tid >> 4;
    const int bglob = bg * 16 + bi;
    const int kg = hc * 16 + ki;
    const int gbase = (dir * 4 + bg) * T_;
    float c = 0.f;

    const float* w0 = w + (0 * 16 + ki) * 256;
    const float* w1 = w + (1 * 16 + ki) * 256;
    const float* w2 = w + (2 * 16 + ki) * 256;
    const float* w3 = w + (3 * 16 + ki) * 256;

    __syncthreads();

    for (int s = 0; s < T_; s++) {
        const int t = dir ? (T_ - 1 - s) : s;
        const float* xpb = g_xproj + ((size_t)dir * T_ + t) * (size_t)(G4H * B_);
        float a0 = xpb[(0 * H_ + kg) * B_ + bglob];
        float a1 = xpb[(1 * H_ + kg) * B_ + bglob];
        float a2 = xpb[(2 * H_ + kg) * B_ + bglob];
        float a3 = xpb[(3 * H_ + kg) * B_ + bglob];

        if (s > 0) {
            if (tid == 0) {
                volatile int* bp = (volatile int*)&g_bar[gbase + s - 1];
                while (*bp < 16) __nanosleep(40);
            }
            __syncthreads();
            const int tprev = dir ? (t + 1) : (t - 1);
            const float* hsrc = g_h + ((size_t)dir * T_ + tprev) * (size_t)(H_ * B_) + bg * 16;
#pragma unroll
            for (int i = 0; i < 4; i++) {
                int f4id = tid + i * 256;       // 0..1023
                int kk = f4id >> 2;
                int b4 = f4id & 3;
                float4 v = *(const float4*)(hsrc + (size_t)kk * B_ + b4 * 4);
                *(float4*)(hs + kk * 16 + b4 * 4) = v;
            }
            __syncthreads();

#pragma unroll 4
            for (int kk = 0; kk < H_; kk += 4) {
                float h0 = hs[(kk + 0) * 16 + bi];
                float h1 = hs[(kk + 1) * 16 + bi];
                float h2 = hs[(kk + 2) * 16 + bi];
                float h3 = hs[(kk + 3) * 16 + bi];
                float4 v0 = *(const float4*)(w0 + kk);
                a0 += v0.x * h0 + v0.y * h1 + v0.z * h2 + v0.w * h3;
                float4 v1 = *(const float4*)(w1 + kk);
                a1 += v1.x * h0 + v1.y * h1 + v1.z * h2 + v1.w * h3;
                float4 v2 = *(const float4*)(w2 + kk);
                a2 += v2.x * h0 + v2.y * h1 + v2.z * h2 + v2.w * h3;
                float4 v3 = *(const float4*)(w3 + kk);
                a3 += v3.x * h0 + v3.y * h1 + v3.z * h2 + v3.w * h3;
            }
        }
        float ig = sigf(a0);
        float fg = sigf(a1);
        float gg = tanhf(a2);
        float og = sigf(a3);
        c = fg * c + ig * gg;
        float h = og * tanhf(c);
        g_h[(((size_t)dir * T_ + t) * H_ + kg) * B_ + bglob] = h;
        __threadfence();
        __syncthreads();
        if (tid == 0) atomicAdd(&g_bar[gbase + s], 1);
    }
}

// ---------------- fc1: inter[t][n][b] = relu(fc1_W[n,:]·hcat[:,b at t] + b[n])
// grid (2 n-tiles, 256 t), block 256. K=512 (dir0 h then dir1 h), 8 chunks of 64.
__global__ void fc1_kernel(const float* __restrict__ W, const float* __restrict__ bias) {
    __shared__ float As[64 * 64];
    __shared__ float Bs[64 * 64];
    const int tid = threadIdx.x;
    const int n0  = blockIdx.x * 64;
    const int t   = blockIdx.y;
    float acc[4][4];
#pragma unroll
    for (int i = 0; i < 4; i++)
#pragma unroll
        for (int j = 0; j < 4; j++) acc[i][j] = 0.f;

    const int lane = tid & 63;
    const int k4b  = tid >> 6;
    const int n_t  = tid >> 4;
    const int b_t  = tid & 15;

    for (int kc = 0; kc < 8; kc++) {
        const int k0 = kc * 64;
        const float* Arow = W + (size_t)(n0 + lane) * 512 + k0;
#pragma unroll
        for (int i = 0; i < 4; i++) {
            int k4 = k4b + i * 4;
            float4 v = *(const float4*)(Arow + k4 * 4);
            As[(k4 * 4 + 0) * 64 + lane] = v.x;
            As[(k4 * 4 + 1) * 64 + lane] = v.y;
            As[(k4 * 4 + 2) * 64 + lane] = v.z;
            As[(k4 * 4 + 3) * 64 + lane] = v.w;
        }
        // B tile: g_h[(k0>>8)][t][k0&255 .. +63][0..63] — layout-identical copy
        const float4* Bsrc = (const float4*)(g_h + (((size_t)(k0 >> 8) * T_ + t) * H_ + (k0 & 255)) * B_);
        float4* Bd = (float4*)Bs;
#pragma unroll
        for (int i = 0; i < 4; i++) Bd[tid + i * 256] = Bsrc[tid + i * 256];
        __syncthreads();

        const float4* A4 = (const float4*)As;
        const float4* B4 = (const float4*)Bs;
#pragma unroll 4
        for (int k = 0; k < 64; k++) {
            float4 a = A4[k * 16 + n_t];
            float4 b = B4[k * 16 + b_t];
            acc[0][0] += a.x * b.x; acc[0][1] += a.x * b.y; acc[0][2] += a.x * b.z; acc[0][3] += a.x * b.w;
            acc[1][0] += a.y * b.x; acc[1][1] += a.y * b.y; acc[1][2] += a.y * b.z; acc[1][3] += a.y * b.w;
            acc[2][0] += a.z * b.x; acc[2][1] += a.z * b.y; acc[2][2] += a.z * b.z; acc[2][3] += a.z * b.w;
            acc[3][0] += a.w * b.x; acc[3][1] += a.w * b.y; acc[3][2] += a.w * b.z; acc[3][3] += a.w * b.w;
        }
        __syncthreads();
    }
#pragma unroll
    for (int j = 0; j < 4; j++) {
        int nn = n0 + n_t * 4 + j;
        float bv = bias[nn];
        float4 o;
        o.x = fmaxf(acc[j][0] + bv, 0.f);
        o.y = fmaxf(acc[j][1] + bv, 0.f);
        o.z = fmaxf(acc[j][2] + bv, 0.f);
        o.w = fmaxf(acc[j][3] + bv, 0.f);
        *(float4*)(g_inter + ((size_t)t * INTER_ + nn) * B_ + b_t * 4) = o;
    }
}

// ---------------- cls: unary[b][t][l] = cls_W[l,:]·inter[t][:,b] + cls_b[l]; pad l=17,18
__global__ void cls_kernel(const float* __restrict__ clsW, const float* __restrict__ clsb) {
    __shared__ float sI[INTER_ * B_];
    __shared__ float sW[NL * INTER_];
    const int t = blockIdx.x;
    const int tid = threadIdx.x;
    const float4* src = (const float4*)(g_inter + (size_t)t * INTER_ * B_);
    float4* dst = (float4*)sI;
#pragma unroll
    for (int i = 0; i < 8; i++) dst[tid + i * 256] = src[tid + i * 256];
    for (int i = tid; i < NL * INTER_; i += 256) sW[i] = clsW[i];
    __syncthreads();

    const int b  = tid & 63;
    const int lg = tid >> 6;
    for (int l = lg; l < NL; l += 4) {
        float acc = clsb[l];
        const float* wr = sW + l * INTER_;
#pragma unroll 8
        for (int n = 0; n < INTER_; n++) acc += wr[n] * sI[n * B_ + b];
        g_unary[((size_t)b * T_ + t) * TL + l] = acc;
    }
    if (tid < 128) {
        int bb = tid & 63;
        int l  = NL + (tid >> 6);
        g_unary[((size_t)bb * T_ + t) * TL + l] = LOW_POT;
    }
}

// ---------------- Viterbi + backtrace (one block per batch element) ---------
__global__ void viterbi_kernel(const float* __restrict__ trans, float* __restrict__ out,
                               int score_off, int label_off) {
    __shared__ float tr[TL * TL];
    __shared__ float s0[TL], s1[TL];
    __shared__ unsigned char bp[T_][TL];
    const int b = blockIdx.x;
    const int tid = threadIdx.x;

    for (int i = tid; i < TL * TL; i += 32) tr[i] = trans[i];
    if (tid < TL) s0[tid] = (tid == START_L) ? 0.f : LOW_POT;
    __syncthreads();

    const float* ub = g_unary + (size_t)b * T_ * TL;
    float* sc = s0;
    float* sn = s1;
    for (int t = 0; t < T_; t++) {
        if (tid < TL) {
            // cand[p] = sc[p] + trans[next=tid][prev=p]; first-index argmax (strict >)
            float best = sc[0] + tr[tid * TL + 0];
            int bpi = 0;
#pragma unroll
            for (int p = 1; p < TL; p++) {
                float v = sc[p] + tr[tid * TL + p];
                if (v > best) { best = v; bpi = p; }
            }
            sn[tid] = best + ub[t * TL + tid];
            bp[t][tid] = (unsigned char)bpi;
        }
        __syncthreads();
        float* tmp = sc; sc = sn; sn = tmp;
    }
    if (tid == 0) {
        float best = sc[0] + tr[END_L * TL + 0];
        int li = 0;
        for (int l = 1; l < TL; l++) {
            float v = sc[l] + tr[END_L * TL + l];
            if (v > best) { best = v; li = l; }
        }
        if (score_off >= 0) out[score_off + b] = best;
        if (label_off >= 0) {
            int cur = li;
            for (int t = T_ - 1; t >= 0; t--) {
                out[label_off + (size_t)b * T_ + t] = (float)cur;
                cur = bp[t][cur];
            }
        }
    }
}

// ---------------- launch -----------------------------------------------------
extern "C" void kernel_launch(void* const* d_in, const int* in_sizes, int n_in,
                              void* d_out, int out_size) {
    const int*   x       = (const int*)d_in[0];
    const float* emb     = (const float*)d_in[1];
    const float* W_ih_f  = (const float*)d_in[2];
    const float* W_hh_f  = (const float*)d_in[3];
    const float* b_f     = (const float*)d_in[4];
    const float* W_ih_b  = (const float*)d_in[5];
    const float* W_hh_b  = (const float*)d_in[6];
    const float* b_b     = (const float*)d_in[7];
    const float* fc1_W   = (const float*)d_in[8];
    const float* fc1_b   = (const float*)d_in[9];
    const float* cls_W   = (const float*)d_in[10];
    const float* cls_b   = (const float*)d_in[11];
    const float* trans   = (const float*)d_in[12];
    float* out = (float*)d_out;

    int score_off = 0, label_off = B_;
    if (out_size == B_ * T_)      { score_off = -1; label_off = 0; }
    else if (out_size == B_)      { label_off = -1; }

    const int lstm_smem = (64 * 256 + 256 * 16) * (int)sizeof(float);  // 81920 B
    cudaFuncSetAttribute(lstm_kernel, cudaFuncAttributeMaxDynamicSharedMemorySize, lstm_smem);

    zero_bar_kernel<<<8, 256>>>();
    xproj_kernel<<<dim3(16, T_, 2), 256>>>(x, emb, W_ih_f, b_f, W_ih_b, b_b);
    lstm_kernel<<<128, 256, lstm_smem>>>(W_hh_f, W_hh_b);
    fc1_kernel<<<dim3(2, T_), 256>>>(fc1_W, fc1_b);
    cls_kernel<<<T_, 256>>>(cls_W, cls_b);
    viterbi_kernel<<<B_, 32>>>(trans, out, score_off, label_off);
}

// round 2
// speedup vs baseline: 1.0411x; 1.0411x over previous
#include <cuda_runtime.h>
#include <cuda_bf16.h>
#include <math.h>
#include <stdint.h>

// Problem constants
#define B_   64
#define T_   256
#define E_   300
#define H_   256
#define G4H  1024      // 4*H
#define INTER_ 128
#define NL   17
#define TL   19        // NUM_LABELS + 2
#define START_L 17
#define END_L   18
#define LOW_POT (-10000.0f)

// ---------------- scratch (device globals; no allocations allowed) ----------
__device__ float g_xproj[(size_t)2 * T_ * G4H * B_];   // [dir][t][n(1024)][b]
__device__ float g_h[(size_t)2 * T_ * H_ * B_];        // [dir][t][k][b]
__device__ float g_inter[(size_t)T_ * INTER_ * B_];    // [t][n(128)][b]
__device__ float g_unary[(size_t)B_ * T_ * TL];        // [b][t][l]
__device__ int   g_bar[2 * 4 * T_];                    // per-(dir,batchgroup) step counters

// ---------------- helpers ----------------------------------------------------
__device__ __forceinline__ uint32_t f2tf32(float x) {
    uint32_t r;
    asm("cvt.rna.tf32.f32 %0, %1;" : "=r"(r) : "f"(x));
    return r;
}
__device__ __forceinline__ void split_tf32(float x, uint32_t& hi, uint32_t& lo) {
    hi = f2tf32(x);
    lo = f2tf32(x - __uint_as_float(hi));
}
__device__ __forceinline__ void mma_tf32(float* d, const uint32_t* a, uint32_t b0, uint32_t b1) {
    asm volatile(
        "mma.sync.aligned.m16n8k8.row.col.f32.tf32.tf32.f32 "
        "{%0,%1,%2,%3}, {%4,%5,%6,%7}, {%8,%9}, {%0,%1,%2,%3};"
        : "+f"(d[0]), "+f"(d[1]), "+f"(d[2]), "+f"(d[3])
        : "r"(a[0]), "r"(a[1]), "r"(a[2]), "r"(a[3]), "r"(b0), "r"(b1));
}

// ---------------- barrier zeroing (graph-replay determinism) ----------------
__global__ void zero_bar_kernel() {
    int i = blockIdx.x * 256 + threadIdx.x;
    if (i < 2 * 4 * T_) g_bar[i] = 0;
}

// =============================================================================
// xproj GEMM (3xTF32): out[dir][t][n][b] = W_ih[n,:]·emb[x[b,t],:] + bias[n]
// grid (8 n-tiles of 128, 256 t, 2 dir), block 256 (8 warps).
// Tile 128(n) x 64(b). K = 300 padded to 320 (10 chunks of 32). Double-buffered.
// smem layout (uint32): Ah[2][32*136], Al[2][32*136], Bh[2][32*72], Bl[2][32*72], tok[64]
// =============================================================================
#define XA_PAD 136
#define XB_PAD 72
#define XA_SZ  (32 * XA_PAD)   // 4352
#define XB_SZ  (32 * XB_PAD)   // 2304
#define X_AH(buf) ((buf) * XA_SZ)
#define X_AL(buf) (2 * XA_SZ + (buf) * XA_SZ)
#define X_BH(buf) (4 * XA_SZ + (buf) * XB_SZ)
#define X_BL(buf) (4 * XA_SZ + 2 * XB_SZ + (buf) * XB_SZ)
#define X_TOK     (4 * XA_SZ + 4 * XB_SZ)
#define X_SMEM_BYTES ((4 * XA_SZ + 4 * XB_SZ + 64) * 4)

__global__ void __launch_bounds__(256, 2)
xproj_kernel(const int* __restrict__ x,
             const float* __restrict__ emb,
             const float* __restrict__ Wf, const float* __restrict__ bf,
             const float* __restrict__ Wb, const float* __restrict__ bb) {
    extern __shared__ uint32_t sm[];
    const int tid  = threadIdx.x;
    const int n0   = blockIdx.x * 128;
    const int t    = blockIdx.y;
    const int dir  = blockIdx.z;
    const float* W    = dir ? Wb : Wf;
    const float* bias = dir ? bb : bf;

    int* tok = (int*)(sm + X_TOK);
    if (tid < 64) tok[tid] = x[tid * T_ + t];
    __syncthreads();

    const int rowA = tid & 127;          // A row within tile
    const int kqA  = tid >> 7;           // 0..1
    const int rowB = tid & 63;           // b index
    const int kqB  = tid >> 6;           // 0..3
    const float* Arow = W + (size_t)(n0 + rowA) * E_;
    const float* Brow = emb + (size_t)tok[rowB] * E_;

    const int wid  = tid >> 5;
    const int lane = tid & 31;
    const int r    = lane >> 2;          // 0..7
    const int cidx = lane & 3;           // 0..3

    float acc[8][4];
#pragma unroll
    for (int i = 0; i < 8; i++)
#pragma unroll
        for (int j = 0; j < 4; j++) acc[i][j] = 0.f;

    float4 av[4];
    float4 bv[2];

    // --- prologue: load + store chunk 0 into buffer 0
#pragma unroll
    for (int j = 0; j < 4; j++) {
        int gk4 = (kqA + 2 * j);                 // chunk 0
        av[j] = (gk4 < 75) ? *(const float4*)(Arow + gk4 * 4) : make_float4(0, 0, 0, 0);
    }
#pragma unroll
    for (int j = 0; j < 2; j++) {
        int gk4 = (kqB + 4 * j);
        bv[j] = (gk4 < 75) ? *(const float4*)(Brow + gk4 * 4) : make_float4(0, 0, 0, 0);
    }
#pragma unroll
    for (int j = 0; j < 4; j++) {
        int kl = (kqA + 2 * j) * 4;
        const float* v = (const float*)&av[j];
#pragma unroll
        for (int c = 0; c < 4; c++) {
            uint32_t hi, lo; split_tf32(v[c], hi, lo);
            sm[X_AH(0) + (kl + c) * XA_PAD + rowA] = hi;
            sm[X_AL(0) + (kl + c) * XA_PAD + rowA] = lo;
        }
    }
#pragma unroll
    for (int j = 0; j < 2; j++) {
        int kl = (kqB + 4 * j) * 4;
        const float* v = (const float*)&bv[j];
#pragma unroll
        for (int c = 0; c < 4; c++) {
            uint32_t hi, lo; split_tf32(v[c], hi, lo);
            sm[X_BH(0) + (kl + c) * XB_PAD + rowB] = hi;
            sm[X_BL(0) + (kl + c) * XB_PAD + rowB] = lo;
        }
    }
    __syncthreads();

    for (int kc = 0; kc < 10; kc++) {
        const int buf = kc & 1;
        // kick off next chunk's global loads
        if (kc < 9) {
#pragma unroll
            for (int j = 0; j < 4; j++) {
                int gk4 = (kc + 1) * 8 + kqA + 2 * j;
                av[j] = (gk4 < 75) ? *(const float4*)(Arow + gk4 * 4) : make_float4(0, 0, 0, 0);
            }
#pragma unroll
            for (int j = 0; j < 2; j++) {
                int gk4 = (kc + 1) * 8 + kqB + 4 * j;
                bv[j] = (gk4 < 75) ? *(const float4*)(Brow + gk4 * 4) : make_float4(0, 0, 0, 0);
            }
        }
        // compute on current buffer
        const uint32_t* AH = sm + X_AH(buf);
        const uint32_t* AL = sm + X_AL(buf);
        const uint32_t* BH = sm + X_BH(buf);
        const uint32_t* BL = sm + X_BL(buf);
        const int row0 = wid * 16 + r;
#pragma unroll
        for (int kk = 0; kk < 4; kk++) {
            const int base = kk * 8 + cidx;
            uint32_t ah[4], al[4];
            ah[0] = AH[base * XA_PAD + row0];
            ah[1] = AH[base * XA_PAD + row0 + 8];
            ah[2] = AH[(base + 4) * XA_PAD + row0];
            ah[3] = AH[(base + 4) * XA_PAD + row0 + 8];
            al[0] = AL[base * XA_PAD + row0];
            al[1] = AL[base * XA_PAD + row0 + 8];
            al[2] = AL[(base + 4) * XA_PAD + row0];
            al[3] = AL[(base + 4) * XA_PAD + row0 + 8];
#pragma unroll
            for (int nt = 0; nt < 8; nt++) {
                const int col = nt * 8 + r;
                uint32_t bh0 = BH[base * XB_PAD + col];
                uint32_t bh1 = BH[(base + 4) * XB_PAD + col];
                uint32_t bl0 = BL[base * XB_PAD + col];
                uint32_t bl1 = BL[(base + 4) * XB_PAD + col];
                mma_tf32(acc[nt], ah, bh0, bh1);
                mma_tf32(acc[nt], al, bh0, bh1);
                mma_tf32(acc[nt], ah, bl0, bl1);
            }
        }
        // store next chunk into other buffer
        if (kc < 9) {
            const int nb = (kc + 1) & 1;
#pragma unroll
            for (int j = 0; j < 4; j++) {
                int kl = (kqA + 2 * j) * 4;
                const float* v = (const float*)&av[j];
#pragma unroll
                for (int c = 0; c < 4; c++) {
                    uint32_t hi, lo; split_tf32(v[c], hi, lo);
                    sm[X_AH(nb) + (kl + c) * XA_PAD + rowA] = hi;
                    sm[X_AL(nb) + (kl + c) * XA_PAD + rowA] = lo;
                }
            }
#pragma unroll
            for (int j = 0; j < 2; j++) {
                int kl = (kqB + 4 * j) * 4;
                const float* v = (const float*)&bv[j];
#pragma unroll
                for (int c = 0; c < 4; c++) {
                    uint32_t hi, lo; split_tf32(v[c], hi, lo);
                    sm[X_BH(nb) + (kl + c) * XB_PAD + rowB] = hi;
                    sm[X_BL(nb) + (kl + c) * XB_PAD + rowB] = lo;
                }
            }
        }
        __syncthreads();
    }

    // epilogue: +bias, write [dir][t][n][b]
    const int gr0 = n0 + wid * 16 + r;
    const int gr1 = gr0 + 8;
    const float bv0 = bias[gr0];
    const float bv1 = bias[gr1];
    float* outb = g_xproj + ((size_t)(dir * T_ + t)) * (G4H * B_);
#pragma unroll
    for (int nt = 0; nt < 8; nt++) {
        const int col = nt * 8 + 2 * cidx;
        float2 o0 = make_float2(acc[nt][0] + bv0, acc[nt][1] + bv0);
        float2 o1 = make_float2(acc[nt][2] + bv1, acc[nt][3] + bv1);
        *(float2*)(outb + (size_t)gr0 * B_ + col) = o0;
        *(float2*)(outb + (size_t)gr1 * B_ + col) = o1;
    }
}

// ---------------- LSTM recurrence (persistent, per-group sync) --------------
__device__ __forceinline__ float sigf(float x) { return 1.0f / (1.0f + expf(-x)); }

__global__ void lstm_kernel(const float* __restrict__ Whf, const float* __restrict__ Whb) {
    extern __shared__ float smf[];
    float* w  = smf;              // [64][256]: row q*16+ki
    float* hs = smf + 64 * 256;   // [256][16]: [kk][bi]

    const int tid = threadIdx.x;
    const int bx  = blockIdx.x;
    const int dir = bx >> 6;
    const int rr_ = bx & 63;
    const int bg  = rr_ >> 4;       // 0..3
    const int hc  = rr_ & 15;       // 0..15
    const float* Wh = dir ? Whb : Whf;

#pragma unroll
    for (int i = 0; i < 16; i++) {
        int f4id = tid + i * 256;
        int rr = f4id >> 6;
        int c4 = f4id & 63;
        int q  = rr >> 4, ki = rr & 15;
        float4 v = *(const float4*)(Wh + ((size_t)(q * H_ + hc * 16 + ki)) * H_ + c4 * 4);
        *(float4*)(w + (size_t)rr * 256 + c4 * 4) = v;
    }

    const int bi = tid & 15;
    const int ki = tid >> 4;
    const int bglob = bg * 16 + bi;
    const int kg = hc * 16 + ki;
    const int gbase = (dir * 4 + bg) * T_;
    float c = 0.f;

    const float* w0 = w + (0 * 16 + ki) * 256;
    const float* w1 = w + (1 * 16 + ki) * 256;
    const float* w2 = w + (2 * 16 + ki) * 256;
    const float* w3 = w + (3 * 16 + ki) * 256;

    __syncthreads();

    for (int s = 0; s < T_; s++) {
        const int t = dir ? (T_ - 1 - s) : s;
        const float* xpb = g_xproj + ((size_t)dir * T_ + t) * (size_t)(G4H * B_);
        float a0 = xpb[(0 * H_ + kg) * B_ + bglob];
        float a1 = xpb[(1 * H_ + kg) * B_ + bglob];
        float a2 = xpb[(2 * H_ + kg) * B_ + bglob];
        float a3 = xpb[(3 * H_ + kg) * B_ + bglob];

        if (s > 0) {
            if (tid == 0) {
                volatile int* bp = (volatile int*)&g_bar[gbase + s - 1];
                while (*bp < 16) { }
            }
            __syncthreads();
            const int tprev = dir ? (t + 1) : (t - 1);
            const float* hsrc = g_h + ((size_t)dir * T_ + tprev) * (size_t)(H_ * B_) + bg * 16;
#pragma unroll
            for (int i = 0; i < 4; i++) {
                int f4id = tid + i * 256;
                int kk = f4id >> 2;
                int b4 = f4id & 3;
                float4 v = *(const float4*)(hsrc + (size_t)kk * B_ + b4 * 4);
                *(float4*)(hs + kk * 16 + b4 * 4) = v;
            }
            __syncthreads();

#pragma unroll 4
            for (int kk = 0; kk < H_; kk += 4) {
                float h0 = hs[(kk + 0) * 16 + bi];
                float h1 = hs[(kk + 1) * 16 + bi];
                float h2 = hs[(kk + 2) * 16 + bi];
                float h3 = hs[(kk + 3) * 16 + bi];
                float4 v0 = *(const float4*)(w0 + kk);
                a0 += v0.x * h0 + v0.y * h1 + v0.z * h2 + v0.w * h3;
                float4 v1 = *(const float4*)(w1 + kk);
                a1 += v1.x * h0 + v1.y * h1 + v1.z * h2 + v1.w * h3;
                float4 v2 = *(const float4*)(w2 + kk);
                a2 += v2.x * h0 + v2.y * h1 + v2.z * h2 + v2.w * h3;
                float4 v3 = *(const float4*)(w3 + kk);
                a3 += v3.x * h0 + v3.y * h1 + v3.z * h2 + v3.w * h3;
            }
        }
        float ig = sigf(a0);
        float fg = sigf(a1);
        float gg = tanhf(a2);
        float og = sigf(a3);
        c = fg * c + ig * gg;
        float h = og * tanhf(c);
        g_h[(((size_t)dir * T_ + t) * H_ + kg) * B_ + bglob] = h;
        __threadfence();
        __syncthreads();
        if (tid == 0) atomicAdd(&g_bar[gbase + s], 1);
    }
}

// =============================================================================
// fc1 (3xTF32): inter[t][n][b] = relu(fc1_W[n,:]·hcat[:,b at t] + b[n])
// grid (256 t), block 256 (8 warps). Tile 128(n) x 64(b), K=512 (16 chunks of 32).
// =============================================================================
__global__ void __launch_bounds__(256, 2)
fc1_kernel(const float* __restrict__ W, const float* __restrict__ bias) {
    extern __shared__ uint32_t sm[];
    const int tid = threadIdx.x;
    const int t   = blockIdx.x;

    const int rowA = tid & 127;
    const int kqA  = tid >> 7;
    const float* Arow = W + (size_t)rowA * 512;

    const int wid  = tid >> 5;
    const int lane = tid & 31;
    const int r    = lane >> 2;
    const int cidx = lane & 3;

    float acc[8][4];
#pragma unroll
    for (int i = 0; i < 8; i++)
#pragma unroll
        for (int j = 0; j < 4; j++) acc[i][j] = 0.f;

    float4 av[4];
    float4 bv[2];

    // prologue chunk 0
#pragma unroll
    for (int j = 0; j < 4; j++) {
        int gk4 = kqA + 2 * j;
        av[j] = *(const float4*)(Arow + gk4 * 4);
    }
#pragma unroll
    for (int j = 0; j < 2; j++) {
        int f4id = tid + j * 256;
        int kl = f4id >> 4, b4 = f4id & 15;
        int kgl = kl;                       // chunk 0
        int d = kgl >> 8, kh = kgl & 255;
        bv[j] = *(const float4*)(g_h + ((size_t)(d * T_ + t) * 256 + kh) * 64 + b4 * 4);
    }
#pragma unroll
    for (int j = 0; j < 4; j++) {
        int kl = (kqA + 2 * j) * 4;
        const float* v = (const float*)&av[j];
#pragma unroll
        for (int c = 0; c < 4; c++) {
            uint32_t hi, lo; split_tf32(v[c], hi, lo);
            sm[X_AH(0) + (kl + c) * XA_PAD + rowA] = hi;
            sm[X_AL(0) + (kl + c) * XA_PAD + rowA] = lo;
        }
    }
#pragma unroll
    for (int j = 0; j < 2; j++) {
        int f4id = tid + j * 256;
        int kl = f4id >> 4, b4 = f4id & 15;
        const float* v = (const float*)&bv[j];
#pragma unroll
        for (int c = 0; c < 4; c++) {
            uint32_t hi, lo; split_tf32(v[c], hi, lo);
            sm[X_BH(0) + kl * XB_PAD + b4 * 4 + c] = hi;
            sm[X_BL(0) + kl * XB_PAD + b4 * 4 + c] = lo;
        }
    }
    __syncthreads();

    for (int kc = 0; kc < 16; kc++) {
        const int buf = kc & 1;
        if (kc < 15) {
#pragma unroll
            for (int j = 0; j < 4; j++) {
                int gk4 = (kc + 1) * 8 + kqA + 2 * j;
                av[j] = *(const float4*)(Arow + gk4 * 4);
            }
#pragma unroll
            for (int j = 0; j < 2; j++) {
                int f4id = tid + j * 256;
                int kl = f4id >> 4, b4 = f4id & 15;
                int kgl = (kc + 1) * 32 + kl;
                int d = kgl >> 8, kh = kgl & 255;
                bv[j] = *(const float4*)(g_h + ((size_t)(d * T_ + t) * 256 + kh) * 64 + b4 * 4);
            }
        }
        const uint32_t* AH = sm + X_AH(buf);
        const uint32_t* AL = sm + X_AL(buf);
        const uint32_t* BH = sm + X_BH(buf);
        const uint32_t* BL = sm + X_BL(buf);
        const int row0 = wid * 16 + r;
#pragma unroll
        for (int kk = 0; kk < 4; kk++) {
            const int base = kk * 8 + cidx;
            uint32_t ah[4], al[4];
            ah[0] = AH[base * XA_PAD + row0];
            ah[1] = AH[base * XA_PAD + row0 + 8];
            ah[2] = AH[(base + 4) * XA_PAD + row0];
            ah[3] = AH[(base + 4) * XA_PAD + row0 + 8];
            al[0] = AL[base * XA_PAD + row0];
            al[1] = AL[base * XA_PAD + row0 + 8];
            al[2] = AL[(base + 4) * XA_PAD + row0];
            al[3] = AL[(base + 4) * XA_PAD + row0 + 8];
#pragma unroll
            for (int nt = 0; nt < 8; nt++) {
                const int col = nt * 8 + r;
                uint32_t bh0 = BH[base * XB_PAD + col];
                uint32_t bh1 = BH[(base + 4) * XB_PAD + col];
                uint32_t bl0 = BL[base * XB_PAD + col];
                uint32_t bl1 = BL[(base + 4) * XB_PAD + col];
                mma_tf32(acc[nt], ah, bh0, bh1);
                mma_tf32(acc[nt], al, bh0, bh1);
                mma_tf32(acc[nt], ah, bl0, bl1);
            }
        }
        if (kc < 15) {
            const int nb = (kc + 1) & 1;
#pragma unroll
            for (int j = 0; j < 4; j++) {
                int kl = (kqA + 2 * j) * 4;
                const float* v = (const float*)&av[j];
#pragma unroll
                for (int c = 0; c < 4; c++) {
                    uint32_t hi, lo; split_tf32(v[c], hi, lo);
                    sm[X_AH(nb) + (kl + c) * XA_PAD + rowA] = hi;
                    sm[X_AL(nb) + (kl + c) * XA_PAD + rowA] = lo;
                }
            }
#pragma unroll
            for (int j = 0; j < 2; j++) {
                int f4id = tid + j * 256;
                int kl = f4id >> 4, b4 = f4id & 15;
                const float* v = (const float*)&bv[j];
#pragma unroll
                for (int c = 0; c < 4; c++) {
                    uint32_t hi, lo; split_tf32(v[c], hi, lo);
                    sm[X_BH(nb) + kl * XB_PAD + b4 * 4 + c] = hi;
                    sm[X_BL(nb) + kl * XB_PAD + b4 * 4 + c] = lo;
                }
            }
        }
        __syncthreads();
    }

    const int gr0 = wid * 16 + r;
    const int gr1 = gr0 + 8;
    const float bv0 = bias[gr0];
    const float bv1 = bias[gr1];
    float* outb = g_inter + (size_t)t * INTER_ * B_;
#pragma unroll
    for (int nt = 0; nt < 8; nt++) {
        const int col = nt * 8 + 2 * cidx;
        float2 o0 = make_float2(fmaxf(acc[nt][0] + bv0, 0.f), fmaxf(acc[nt][1] + bv0, 0.f));
        float2 o1 = make_float2(fmaxf(acc[nt][2] + bv1, 0.f), fmaxf(acc[nt][3] + bv1, 0.f));
        *(float2*)(outb + (size_t)gr0 * B_ + col) = o0;
        *(float2*)(outb + (size_t)gr1 * B_ + col) = o1;
    }
}

// ---------------- cls: unary[b][t][l] = cls_W[l,:]·inter[t][:,b] + cls_b[l] --
__global__ void cls_kernel(const float* __restrict__ clsW, const float* __restrict__ clsb) {
    __shared__ float sI[INTER_ * B_];
    __shared__ float sW[NL * INTER_];
    const int t = blockIdx.x;
    const int tid = threadIdx.x;
    const float4* src = (const float4*)(g_inter + (size_t)t * INTER_ * B_);
    float4* dst = (float4*)sI;
#pragma unroll
    for (int i = 0; i < 8; i++) dst[tid + i * 256] = src[tid + i * 256];
    for (int i = tid; i < NL * INTER_; i += 256) sW[i] = clsW[i];
    __syncthreads();

    const int b  = tid & 63;
    const int lg = tid >> 6;
    for (int l = lg; l < NL; l += 4) {
        float acc = clsb[l];
        const float* wr = sW + l * INTER_;
#pragma unroll 8
        for (int n = 0; n < INTER_; n++) acc += wr[n] * sI[n * B_ + b];
        g_unary[((size_t)b * T_ + t) * TL + l] = acc;
    }
    if (tid < 128) {
        int bb = tid & 63;
        int l  = NL + (tid >> 6);
        g_unary[((size_t)bb * T_ + t) * TL + l] = LOW_POT;
    }
}

// ---------------- Viterbi + backtrace (one block per batch element) ---------
__global__ void viterbi_kernel(const float* __restrict__ trans, float* __restrict__ out,
                               int score_off, int label_off) {
    __shared__ float tr[TL * TL];
    __shared__ float s0[TL], s1[TL];
    __shared__ unsigned char bp[T_][TL];
    const int b = blockIdx.x;
    const int tid = threadIdx.x;

    for (int i = tid; i < TL * TL; i += 32) tr[i] = trans[i];
    if (tid < TL) s0[tid] = (tid == START_L) ? 0.f : LOW_POT;
    __syncthreads();

    const float* ub = g_unary + (size_t)b * T_ * TL;
    float* sc = s0;
    float* sn = s1;
    for (int t = 0; t < T_; t++) {
        if (tid < TL) {
            float best = sc[0] + tr[tid * TL + 0];
            int bpi = 0;
#pragma unroll
            for (int p = 1; p < TL; p++) {
                float v = sc[p] + tr[tid * TL + p];
                if (v > best) { best = v; bpi = p; }
            }
            sn[tid] = best + ub[t * TL + tid];
            bp[t][tid] = (unsigned char)bpi;
        }
        __syncthreads();
        float* tmp = sc; sc = sn; sn = tmp;
    }
    if (tid == 0) {
        float best = sc[0] + tr[END_L * TL + 0];
        int li = 0;
        for (int l = 1; l < TL; l++) {
            float v = sc[l] + tr[END_L * TL + l];
            if (v > best) { best = v; li = l; }
        }
        if (score_off >= 0) out[score_off + b] = best;
        if (label_off >= 0) {
            int cur = li;
            for (int t = T_ - 1; t >= 0; t--) {
                out[label_off + (size_t)b * T_ + t] = (float)cur;
                cur = bp[t][cur];
            }
        }
    }
}

// ---------------- launch -----------------------------------------------------
extern "C" void kernel_launch(void* const* d_in, const int* in_sizes, int n_in,
                              void* d_out, int out_size) {
    const int*   x       = (const int*)d_in[0];
    const float* emb     = (const float*)d_in[1];
    const float* W_ih_f  = (const float*)d_in[2];
    const float* W_hh_f  = (const float*)d_in[3];
    const float* b_f     = (const float*)d_in[4];
    const float* W_ih_b  = (const float*)d_in[5];
    const float* W_hh_b  = (const float*)d_in[6];
    const float* b_b     = (const float*)d_in[7];
    const float* fc1_W   = (const float*)d_in[8];
    const float* fc1_b   = (const float*)d_in[9];
    const float* cls_W   = (const float*)d_in[10];
    const float* cls_b   = (const float*)d_in[11];
    const float* trans   = (const float*)d_in[12];
    float* out = (float*)d_out;

    int score_off = 0, label_off = B_;
    if (out_size == B_ * T_)      { score_off = -1; label_off = 0; }
    else if (out_size == B_)      { label_off = -1; }

    const int lstm_smem = (64 * 256 + 256 * 16) * (int)sizeof(float);  // 81920 B
    cudaFuncSetAttribute(lstm_kernel, cudaFuncAttributeMaxDynamicSharedMemorySize, lstm_smem);
    cudaFuncSetAttribute(xproj_kernel, cudaFuncAttributeMaxDynamicSharedMemorySize, X_SMEM_BYTES);
    cudaFuncSetAttribute(fc1_kernel, cudaFuncAttributeMaxDynamicSharedMemorySize, X_SMEM_BYTES);

    zero_bar_kernel<<<8, 256>>>();
    xproj_kernel<<<dim3(8, T_, 2), 256, X_SMEM_BYTES>>>(x, emb, W_ih_f, b_f, W_ih_b, b_b);
    lstm_kernel<<<128, 256, lstm_smem>>>(W_hh_f, W_hh_b);
    fc1_kernel<<<T_, 256, X_SMEM_BYTES>>>(fc1_W, fc1_b);
    cls_kernel<<<T_, 256>>>(cls_W, cls_b);
    viterbi_kernel<<<B_, 32>>>(trans, out, score_off, label_off);
}